// round 11
// baseline (speedup 1.0000x reference)
#include <cuda_runtime.h>
#include <cuda_bf16.h>
#include <cstdint>

// NonLocalBlock on GB300 (plain sm_103 ISA): conv1(1x1, fused bf16 hi/lo split
// + row norms) -> flash self-attention via mma.sync bf16 HMMA, hi/lo 3-pass,
// fixed-base softmax (Cauchy-Schwarz bound), cp.async double-buffered K chunks
// -> conv2 + scale + residual.  B=8, C=256, C2=128, N=4096, fp32 I/O.

namespace {
constexpr int B_  = 8;
constexpr int C_  = 256;
constexpr int C2_ = 128;
constexpr int N_  = 4096;
constexpr int QT  = 128;          // queries per block
constexpr int KT  = 64;           // keys per chunk
constexpr int NCHUNK = N_ / KT;   // 64

// attention smem (bytes): resident Q hi/lo + double-buffered K chunk hi/lo.
// row stride 256B (128 feats bf16), 16B chunks XOR-swizzled by (row&7).
constexpr int OFF_QHI = 0;            // 128 x 256B = 32KB
constexpr int OFF_QLO = 32768;        // 32KB
constexpr int OFF_KB  = 65536;        // 2 bufs x (16KB hi + 16KB lo)
constexpr int KBUF_SZ = 32768;
constexpr int KLO     = 16384;        // lo offset within a buf
constexpr int ATTN_DYN = OFF_KB + 2 * KBUF_SZ;   // 131072
}

__device__ __nv_bfloat16 g_yhi[B_ * N_ * C2_];  // conv1 out, hi bf16, [b][n][c2]
__device__ __nv_bfloat16 g_ylo[B_ * N_ * C2_];  // residual lo bf16
__device__ float g_att[B_ * N_ * C2_];          // attention out (torch-bug flat order)
__device__ float g_nrm[B_ * N_];                // ||y_n||^2
__device__ float g_R[B_];                       // max_n ||y_n||^2

// ---------------------------------------------------------------------------
// helpers
// ---------------------------------------------------------------------------
__device__ __forceinline__ uint32_t s2u(const void* p) {
    uint32_t a;
    asm("{ .reg .u64 t; cvta.to.shared.u64 t, %1; cvt.u32.u64 %0, t; }" : "=r"(a) : "l"(p));
    return a;
}

__device__ __forceinline__ uint32_t packbf(__nv_bfloat16 a, __nv_bfloat16 b) {
    __nv_bfloat162 t = __halves2bfloat162(a, b);
    return *reinterpret_cast<uint32_t*>(&t);
}

// hi/lo split of a float pair -> two packed bf16x2
__device__ __forceinline__ uint32_t split2(float a, float b, uint32_t& lo) {
    __nv_bfloat16 ha = __float2bfloat16(a), hb = __float2bfloat16(b);
    lo = packbf(__float2bfloat16(a - __bfloat162float(ha)),
                __float2bfloat16(b - __bfloat162float(hb)));
    return packbf(ha, hb);
}

__device__ __forceinline__ void ldsm4(uint32_t* r, uint32_t addr) {
    asm volatile("ldmatrix.sync.aligned.m8n8.x4.shared.b16 {%0,%1,%2,%3}, [%4];"
                 : "=r"(r[0]), "=r"(r[1]), "=r"(r[2]), "=r"(r[3]) : "r"(addr));
}

__device__ __forceinline__ void ldsm4t(uint32_t* r, uint32_t addr) {
    asm volatile("ldmatrix.sync.aligned.m8n8.x4.trans.shared.b16 {%0,%1,%2,%3}, [%4];"
                 : "=r"(r[0]), "=r"(r[1]), "=r"(r[2]), "=r"(r[3]) : "r"(addr));
}

__device__ __forceinline__ void mma16816(float* d, const uint32_t* a, const uint32_t* b) {
    asm volatile(
        "mma.sync.aligned.m16n8k16.row.col.f32.bf16.bf16.f32 "
        "{%0,%1,%2,%3}, {%4,%5,%6,%7}, {%8,%9}, {%0,%1,%2,%3};"
        : "+f"(d[0]), "+f"(d[1]), "+f"(d[2]), "+f"(d[3])
        : "r"(a[0]), "r"(a[1]), "r"(a[2]), "r"(a[3]), "r"(b[0]), "r"(b[1]));
}

__device__ __forceinline__ void cpasync16(uint32_t saddr, const void* gaddr) {
    asm volatile("cp.async.cg.shared.global [%0], [%1], 16;"
                 :: "r"(saddr), "l"(gaddr) : "memory");
}

// ---------------------------------------------------------------------------
__global__ void init_kernel() {
    if (threadIdx.x < B_) g_R[threadIdx.x] = 0.f;
}

// ---------------------------------------------------------------------------
// conv1: y[b][n][o] = b1[o] + sum_c x[b][c][n] * W1[o][c]
// Epilogue: bf16 hi/lo split to g_yhi/g_ylo, row norms to g_nrm, max to g_R.
// ---------------------------------------------------------------------------
__global__ __launch_bounds__(256) void conv1_kernel(const float* __restrict__ x,
                                                    const float* __restrict__ W1,
                                                    const float* __restrict__ b1) {
    __shared__ float Xs[32 * 68];
    __shared__ float Wt[32 * 132];
    __shared__ float Rmx[16];

    const int t  = threadIdx.x;
    const int n0 = blockIdx.x * 64;
    const int b  = blockIdx.y;
    const int ty = t >> 4, tx = t & 15;
    const int r0 = ty * 4;
    const int o0 = tx * 8;
    const float* xb = x + (size_t)b * C_ * N_;

    float acc[4][8];
#pragma unroll
    for (int i = 0; i < 4; i++)
#pragma unroll
        for (int j = 0; j < 8; j++) acc[i][j] = 0.f;

    for (int c0 = 0; c0 < C_; c0 += 32) {
        __syncthreads();
        for (int e = t; e < 32 * 16; e += 256) {
            int cc = e >> 4, k4 = (e & 15) << 2;
            *(float4*)&Xs[cc * 68 + k4] =
                *(const float4*)(xb + (size_t)(c0 + cc) * N_ + n0 + k4);
        }
        for (int e = t; e < 128 * 8; e += 256) {
            int o = e >> 3, c4 = (e & 7) << 2;
            float4 w = *(const float4*)(W1 + (size_t)o * C_ + c0 + c4);
            Wt[(c4 + 0) * 132 + o] = w.x;
            Wt[(c4 + 1) * 132 + o] = w.y;
            Wt[(c4 + 2) * 132 + o] = w.z;
            Wt[(c4 + 3) * 132 + o] = w.w;
        }
        __syncthreads();
#pragma unroll 8
        for (int cc = 0; cc < 32; cc++) {
            float xv[4];
#pragma unroll
            for (int i = 0; i < 4; i++) xv[i] = Xs[cc * 68 + r0 + i];
            float4 wa = *(float4*)&Wt[cc * 132 + o0];
            float4 wb = *(float4*)&Wt[cc * 132 + o0 + 4];
            float wv[8] = {wa.x, wa.y, wa.z, wa.w, wb.x, wb.y, wb.z, wb.w};
#pragma unroll
            for (int i = 0; i < 4; i++)
#pragma unroll
                for (int j = 0; j < 8; j++) acc[i][j] += xv[i] * wv[j];
        }
    }

    float bv[8];
#pragma unroll
    for (int j = 0; j < 8; j++) bv[j] = b1[o0 + j];

    float nsum[4];
#pragma unroll
    for (int i = 0; i < 4; i++) {
        float v[8];
        float s = 0.f;
#pragma unroll
        for (int j = 0; j < 8; j++) {
            v[j] = acc[i][j] + bv[j];
            s += v[j] * v[j];
        }
        nsum[i] = s;
        uint32_t hw[4], lw[4];
#pragma unroll
        for (int e = 0; e < 4; e++) hw[e] = split2(v[2 * e], v[2 * e + 1], lw[e]);
        const size_t idx = (size_t)(b * N_ + n0 + r0 + i) * C2_ + o0;
        *(uint4*)(g_yhi + idx) = make_uint4(hw[0], hw[1], hw[2], hw[3]);
        *(uint4*)(g_ylo + idx) = make_uint4(lw[0], lw[1], lw[2], lw[3]);
    }

    // reduce norms over the 16 tx lanes (same ty = 16 consecutive lanes)
#pragma unroll
    for (int i = 0; i < 4; i++) {
#pragma unroll
        for (int off = 8; off > 0; off >>= 1)
            nsum[i] += __shfl_xor_sync(0xffffffffu, nsum[i], off);
    }
    if (tx == 0) {
        float mx = 0.f;
#pragma unroll
        for (int i = 0; i < 4; i++) {
            g_nrm[(size_t)b * N_ + n0 + r0 + i] = nsum[i];
            mx = fmaxf(mx, nsum[i]);
        }
        Rmx[ty] = mx;
    }
    __syncthreads();
    if (t == 0) {
        float mx = Rmx[0];
#pragma unroll
        for (int i = 1; i < 16; i++) mx = fmaxf(mx, Rmx[i]);
        atomicMax((int*)&g_R[b], __float_as_int(mx));
    }
}

// ---------------------------------------------------------------------------
// mma.sync flash attention, cp.async double-buffered K chunks.
// 8 warps; warp w owns query rows w*16..w*16+15. Q-hi frags register-resident.
// ---------------------------------------------------------------------------
__global__ __launch_bounds__(256, 1) void attn_mma_kernel() {
    extern __shared__ __align__(16) char sm[];
    const uint32_t sb = s2u(sm);

    const int t = threadIdx.x;
    const int w = t >> 5, lane = t & 31;
    const int n0 = blockIdx.x * QT;
    const int b  = blockIdx.y;
    const __nv_bfloat16* yhib = g_yhi + (size_t)b * N_ * C2_;
    const __nv_bfloat16* ylob = g_ylo + (size_t)b * N_ * C2_;

    // fixed softmax bases for this thread's two rows
    const int r0 = w * 16 + (lane >> 2);
    const int r1 = r0 + 8;
    const float Rb = g_R[b];
    const float mt0 = sqrtf(g_nrm[(size_t)b * N_ + n0 + r0] * Rb);
    const float mt1 = sqrtf(g_nrm[(size_t)b * N_ + n0 + r1] * Rb);

    // prefetch K chunk 0 into buf 0 (hi+lo), async
    {
        const int j = t >> 2, q = t & 3;
        const int j7 = j & 7;
        const __nv_bfloat16* srch = yhib + (size_t)j * C2_;
        const __nv_bfloat16* srcl = ylob + (size_t)j * C2_;
#pragma unroll
        for (int i = 0; i < 4; i++) {
            const int c16 = q * 4 + i;
            const uint32_t off = (uint32_t)j * 256 + ((c16 ^ j7) << 4);
            cpasync16(sb + OFF_KB + off,       srch + c16 * 8);
            cpasync16(sb + OFF_KB + KLO + off, srcl + c16 * 8);
        }
    }
    asm volatile("cp.async.commit_group;" ::: "memory");

    // ---- stage Q tile (pre-converted bf16) into resident smem ----
    {
        const int row = t >> 1, half = t & 1;
        const __nv_bfloat16* srch = yhib + (size_t)(n0 + row) * C2_;
        const __nv_bfloat16* srcl = ylob + (size_t)(n0 + row) * C2_;
        const int r7 = row & 7;
#pragma unroll
        for (int f = 0; f < 8; f++) {
            const int c16 = half * 8 + f;
            const uint32_t off = (uint32_t)row * 256 + ((c16 ^ r7) << 4);
            *(uint4*)(sm + OFF_QHI + off) = *(const uint4*)(srch + c16 * 8);
            *(uint4*)(sm + OFF_QLO + off) = *(const uint4*)(srcl + c16 * 8);
        }
    }
    __syncthreads();

    // ldmatrix lane-address precompute
    const int laneh = lane >> 4;
    const int rowA  = w * 16 + (lane & 15);
    const int rA7   = rowA & 7;
    const uint32_t aQhi = sb + OFF_QHI + (uint32_t)rowA * 256;
    const uint32_t aQlo = sb + OFF_QLO + (uint32_t)rowA * 256;
    const int keyS = (lane & 7) + (laneh << 3);
    const int cS   = (lane >> 3) & 1;
    const int l7   = lane & 7;
    const int keyV = lane & 15;

    // hoist Q-hi fragments (chunk-invariant): 8 ktiles x 4 regs
    uint32_t qh[8][4];
#pragma unroll
    for (int k = 0; k < 8; k++)
        ldsm4(qh[k], aQhi + (((2 * k + laneh) ^ rA7) << 4));

    float o[16][4];
#pragma unroll
    for (int n = 0; n < 16; n++)
#pragma unroll
        for (int e = 0; e < 4; e++) o[n][e] = 0.f;
    float lacc0 = 0.f, lacc1 = 0.f;

    for (int ci = 0; ci < NCHUNK; ci++) {
        __syncthreads();  // prior reads of the buffer about to be overwritten done

        // prefetch chunk ci+1 into the other buffer
        if (ci + 1 < NCHUNK) {
            const int j = t >> 2, q = t & 3;
            const int j7 = j & 7;
            const uint32_t base = sb + OFF_KB + (uint32_t)((ci + 1) & 1) * KBUF_SZ;
            const __nv_bfloat16* srch = yhib + (size_t)((ci + 1) * KT + j) * C2_;
            const __nv_bfloat16* srcl = ylob + (size_t)((ci + 1) * KT + j) * C2_;
#pragma unroll
            for (int i = 0; i < 4; i++) {
                const int c16 = q * 4 + i;
                const uint32_t off = (uint32_t)j * 256 + ((c16 ^ j7) << 4);
                cpasync16(base + off,       srch + c16 * 8);
                cpasync16(base + KLO + off, srcl + c16 * 8);
            }
            asm volatile("cp.async.commit_group;" ::: "memory");
            asm volatile("cp.async.wait_group 1;" ::: "memory");
        } else {
            asm volatile("cp.async.wait_group 0;" ::: "memory");
        }
        __syncthreads();  // chunk ci visible to all warps

        const uint32_t bufh = sb + OFF_KB + (uint32_t)(ci & 1) * KBUF_SZ;
        const uint32_t bufl = bufh + KLO;

        // ---- S = Q K^T : 3-pass hi/lo ----
        float s[8][4];
#pragma unroll
        for (int n = 0; n < 8; n++)
#pragma unroll
            for (int e = 0; e < 4; e++) s[n][e] = 0.f;

#pragma unroll
        for (int k = 0; k < 8; k++) {
            uint32_t ql[4];
            ldsm4(ql, aQlo + (((2 * k + laneh) ^ rA7) << 4));
            const int cB = 2 * k + cS;
#pragma unroll
            for (int np = 0; np < 4; np++) {
                const uint32_t rb = (uint32_t)(np * 16 + keyS) * 256 +
                                    (uint32_t)((cB ^ l7) << 4);
                uint32_t bh[4], bl[4];
                ldsm4(bh, bufh + rb);
                ldsm4(bl, bufl + rb);
                mma16816(s[2 * np],     qh[k], bh);
                mma16816(s[2 * np + 1], qh[k], bh + 2);
                mma16816(s[2 * np],     qh[k], bl);
                mma16816(s[2 * np + 1], qh[k], bl + 2);
                mma16816(s[2 * np],     ql, bh);
                mma16816(s[2 * np + 1], ql, bh + 2);
            }
        }

        // ---- softmax (fixed base) + pack P into A-fragments hi/lo ----
        uint32_t ph[16], pl[16];
#pragma unroll
        for (int j = 0; j < 8; j++) {
            float p0 = __expf(s[j][0] - mt0);
            float p1 = __expf(s[j][1] - mt0);
            float p2 = __expf(s[j][2] - mt1);
            float p3 = __expf(s[j][3] - mt1);
            lacc0 += p0 + p1;
            lacc1 += p2 + p3;
            const int idx = (j >> 1) * 4 + (j & 1) * 2;
            ph[idx]     = split2(p0, p1, pl[idx]);
            ph[idx + 1] = split2(p2, p3, pl[idx + 1]);
        }

        // ---- O += P V : V via ldmatrix.trans on the same K tile ----
#pragma unroll
        for (int fp = 0; fp < 8; fp++) {
#pragma unroll
            for (int K = 0; K < 4; K++) {
                const uint32_t rb = (uint32_t)(K * 16 + keyV) * 256 +
                                    (uint32_t)(((fp * 2 + laneh) ^ l7) << 4);
                uint32_t vh[4], vl[4];
                ldsm4t(vh, bufh + rb);
                ldsm4t(vl, bufl + rb);
                mma16816(o[2 * fp],     &ph[4 * K], vh);
                mma16816(o[2 * fp + 1], &ph[4 * K], vh + 2);
                mma16816(o[2 * fp],     &ph[4 * K], vl);
                mma16816(o[2 * fp + 1], &ph[4 * K], vl + 2);
                mma16816(o[2 * fp],     &pl[4 * K], vh);
                mma16816(o[2 * fp + 1], &pl[4 * K], vh + 2);
            }
        }
    }

    // ---- finalize l ----
    lacc0 += __shfl_xor_sync(0xffffffffu, lacc0, 1);
    lacc0 += __shfl_xor_sync(0xffffffffu, lacc0, 2);
    lacc1 += __shfl_xor_sync(0xffffffffu, lacc1, 1);
    lacc1 += __shfl_xor_sync(0xffffffffu, lacc1, 2);
    const float inv0 = 1.0f / lacc0;
    const float inv1 = 1.0f / lacc1;

    // ---- epilogue: normalize, store flat [n][c2] (torch-bug order) ----
    float* dst0 = g_att + (size_t)b * N_ * C2_ + (size_t)(n0 + r0) * C2_;
    float* dst1 = g_att + (size_t)b * N_ * C2_ + (size_t)(n0 + r1) * C2_;
    const int fbase = 2 * (lane & 3);
#pragma unroll
    for (int n = 0; n < 16; n++) {
        const int f = n * 8 + fbase;
        *(float2*)(dst0 + f) = make_float2(o[n][0] * inv0, o[n][1] * inv0);
        *(float2*)(dst1 + f) = make_float2(o[n][2] * inv1, o[n][3] * inv1);
    }
}

// ---------------------------------------------------------------------------
// conv2 + scale + residual
// ---------------------------------------------------------------------------
__global__ __launch_bounds__(256) void conv2_kernel(const float* __restrict__ x,
                                                    const float* __restrict__ W2,
                                                    const float* __restrict__ b2,
                                                    const float* __restrict__ scale,
                                                    float* __restrict__ out) {
    extern __shared__ float smf[];
    float* Ss = smf;
    float* Ws = smf + 128 * 68;

    const int t  = threadIdx.x;
    const int n0 = blockIdx.x * 64;
    const int o0 = blockIdx.y * 64;
    const int b  = blockIdx.z;
    const int ty = t >> 4, tx = t & 15;
    const int r0 = ty * 4;
    const int c0 = tx * 4;
    const float* sbp = g_att + (size_t)b * N_ * C2_;

    for (int e = t; e < 128 * 16; e += 256) {
        int row = e >> 4, k4 = (e & 15) << 2;
        *(float4*)&Ss[row * 68 + k4] = *(const float4*)(sbp + (size_t)row * N_ + n0 + k4);
    }
    for (int e = t; e < 64 * 32; e += 256) {
        int o = e >> 5, c4 = (e & 31) << 2;
        *(float4*)&Ws[o * 132 + c4] = *(const float4*)(W2 + (size_t)(o0 + o) * C2_ + c4);
    }
    __syncthreads();

    float acc[4][4];
#pragma unroll
    for (int i = 0; i < 4; i++)
#pragma unroll
        for (int j = 0; j < 4; j++) acc[i][j] = 0.f;

#pragma unroll 4
    for (int c = 0; c < 128; c++) {
        float wv[4];
#pragma unroll
        for (int i = 0; i < 4; i++) wv[i] = Ws[(r0 + i) * 132 + c];
        float4 sv = *(float4*)&Ss[c * 68 + c0];
#pragma unroll
        for (int i = 0; i < 4; i++) {
            acc[i][0] += wv[i] * sv.x;
            acc[i][1] += wv[i] * sv.y;
            acc[i][2] += wv[i] * sv.z;
            acc[i][3] += wv[i] * sv.w;
        }
    }

#pragma unroll
    for (int i = 0; i < 4; i++) {
        int oo = o0 + r0 + i;
        float sc = scale[oo];
        float bi = b2[oo];
        size_t idx = ((size_t)(b * C_ + oo)) * N_ + n0 + c0;
        float4 xv = *(const float4*)(x + idx);
        float4 r;
        r.x = sc * (acc[i][0] + bi) + xv.x;
        r.y = sc * (acc[i][1] + bi) + xv.y;
        r.z = sc * (acc[i][2] + bi) + xv.z;
        r.w = sc * (acc[i][3] + bi) + xv.w;
        *(float4*)(out + idx) = r;
    }
}

// ---------------------------------------------------------------------------
extern "C" void kernel_launch(void* const* d_in, const int* in_sizes, int n_in,
                              void* d_out, int out_size) {
    const float* x     = (const float*)d_in[0];
    const float* W1    = (const float*)d_in[1];
    const float* b1    = (const float*)d_in[2];
    const float* W2    = (const float*)d_in[3];
    const float* b2    = (const float*)d_in[4];
    const float* scale = (const float*)d_in[5];
    float* out = (float*)d_out;

    constexpr int CONV2_SMEM = (128 * 68 + 64 * 132) * 4;
    cudaFuncSetAttribute(attn_mma_kernel, cudaFuncAttributeMaxDynamicSharedMemorySize, ATTN_DYN);
    cudaFuncSetAttribute(conv2_kernel, cudaFuncAttributeMaxDynamicSharedMemorySize, CONV2_SMEM);

    init_kernel<<<1, 32>>>();
    conv1_kernel<<<dim3(N_ / 64, B_), 256>>>(x, W1, b1);
    attn_mma_kernel<<<dim3(N_ / QT, B_), 256, ATTN_DYN>>>();
    conv2_kernel<<<dim3(N_ / 64, C_ / 64, B_), 256, CONV2_SMEM>>>(x, W2, b2, scale, out);
}

// round 12
// speedup vs baseline: 1.5813x; 1.5813x over previous
#include <cuda_runtime.h>
#include <cuda_bf16.h>
#include <cstdint>

// NonLocalBlock on GB300 (plain sm_103 ISA): conv1(1x1, fused bf16 hi/lo split
// + row norms) -> flash self-attention via mma.sync bf16 HMMA, hi/lo 3-pass,
// fixed-base softmax (Cauchy-Schwarz bound), cp.async double-buffered K chunks,
// Q fragments reloaded from smem (no register hoist -> no spills)
// -> conv2 + scale + residual.  B=8, C=256, C2=128, N=4096, fp32 I/O.

namespace {
constexpr int B_  = 8;
constexpr int C_  = 256;
constexpr int C2_ = 128;
constexpr int N_  = 4096;
constexpr int QT  = 128;          // queries per block
constexpr int KT  = 64;           // keys per chunk
constexpr int NCHUNK = N_ / KT;   // 64

// attention smem (bytes): resident Q hi/lo + double-buffered K chunk hi/lo.
// row stride 256B (128 feats bf16), 16B chunks XOR-swizzled by (row&7).
constexpr int OFF_QHI = 0;            // 128 x 256B = 32KB
constexpr int OFF_QLO = 32768;        // 32KB
constexpr int OFF_KB  = 65536;        // 2 bufs x (16KB hi + 16KB lo)
constexpr int KBUF_SZ = 32768;
constexpr int KLO     = 16384;        // lo offset within a buf
constexpr int ATTN_DYN = OFF_KB + 2 * KBUF_SZ;   // 131072
}

__device__ __nv_bfloat16 g_yhi[B_ * N_ * C2_];  // conv1 out, hi bf16, [b][n][c2]
__device__ __nv_bfloat16 g_ylo[B_ * N_ * C2_];  // residual lo bf16
__device__ float g_att[B_ * N_ * C2_];          // attention out (torch-bug flat order)
__device__ float g_nrm[B_ * N_];                // ||y_n||^2
__device__ float g_R[B_];                       // max_n ||y_n||^2

// ---------------------------------------------------------------------------
// helpers
// ---------------------------------------------------------------------------
__device__ __forceinline__ uint32_t s2u(const void* p) {
    uint32_t a;
    asm("{ .reg .u64 t; cvta.to.shared.u64 t, %1; cvt.u32.u64 %0, t; }" : "=r"(a) : "l"(p));
    return a;
}

__device__ __forceinline__ uint32_t packbf(__nv_bfloat16 a, __nv_bfloat16 b) {
    __nv_bfloat162 t = __halves2bfloat162(a, b);
    return *reinterpret_cast<uint32_t*>(&t);
}

// hi/lo split of a float pair -> two packed bf16x2
__device__ __forceinline__ uint32_t split2(float a, float b, uint32_t& lo) {
    __nv_bfloat16 ha = __float2bfloat16(a), hb = __float2bfloat16(b);
    lo = packbf(__float2bfloat16(a - __bfloat162float(ha)),
                __float2bfloat16(b - __bfloat162float(hb)));
    return packbf(ha, hb);
}

__device__ __forceinline__ void ldsm4(uint32_t* r, uint32_t addr) {
    asm volatile("ldmatrix.sync.aligned.m8n8.x4.shared.b16 {%0,%1,%2,%3}, [%4];"
                 : "=r"(r[0]), "=r"(r[1]), "=r"(r[2]), "=r"(r[3]) : "r"(addr));
}

__device__ __forceinline__ void ldsm4t(uint32_t* r, uint32_t addr) {
    asm volatile("ldmatrix.sync.aligned.m8n8.x4.trans.shared.b16 {%0,%1,%2,%3}, [%4];"
                 : "=r"(r[0]), "=r"(r[1]), "=r"(r[2]), "=r"(r[3]) : "r"(addr));
}

__device__ __forceinline__ void mma16816(float* d, const uint32_t* a, const uint32_t* b) {
    asm volatile(
        "mma.sync.aligned.m16n8k16.row.col.f32.bf16.bf16.f32 "
        "{%0,%1,%2,%3}, {%4,%5,%6,%7}, {%8,%9}, {%0,%1,%2,%3};"
        : "+f"(d[0]), "+f"(d[1]), "+f"(d[2]), "+f"(d[3])
        : "r"(a[0]), "r"(a[1]), "r"(a[2]), "r"(a[3]), "r"(b[0]), "r"(b[1]));
}

__device__ __forceinline__ void cpasync16(uint32_t saddr, const void* gaddr) {
    asm volatile("cp.async.cg.shared.global [%0], [%1], 16;"
                 :: "r"(saddr), "l"(gaddr) : "memory");
}

// ---------------------------------------------------------------------------
__global__ void init_kernel() {
    if (threadIdx.x < B_) g_R[threadIdx.x] = 0.f;
}

// ---------------------------------------------------------------------------
// conv1: y[b][n][o] = b1[o] + sum_c x[b][c][n] * W1[o][c]
// Epilogue: bf16 hi/lo split to g_yhi/g_ylo, row norms to g_nrm, max to g_R.
// ---------------------------------------------------------------------------
__global__ __launch_bounds__(256) void conv1_kernel(const float* __restrict__ x,
                                                    const float* __restrict__ W1,
                                                    const float* __restrict__ b1) {
    __shared__ float Xs[32 * 68];
    __shared__ float Wt[32 * 132];
    __shared__ float Rmx[16];

    const int t  = threadIdx.x;
    const int n0 = blockIdx.x * 64;
    const int b  = blockIdx.y;
    const int ty = t >> 4, tx = t & 15;
    const int r0 = ty * 4;
    const int o0 = tx * 8;
    const float* xb = x + (size_t)b * C_ * N_;

    float acc[4][8];
#pragma unroll
    for (int i = 0; i < 4; i++)
#pragma unroll
        for (int j = 0; j < 8; j++) acc[i][j] = 0.f;

    for (int c0 = 0; c0 < C_; c0 += 32) {
        __syncthreads();
        for (int e = t; e < 32 * 16; e += 256) {
            int cc = e >> 4, k4 = (e & 15) << 2;
            *(float4*)&Xs[cc * 68 + k4] =
                *(const float4*)(xb + (size_t)(c0 + cc) * N_ + n0 + k4);
        }
        for (int e = t; e < 128 * 8; e += 256) {
            int o = e >> 3, c4 = (e & 7) << 2;
            float4 w = *(const float4*)(W1 + (size_t)o * C_ + c0 + c4);
            Wt[(c4 + 0) * 132 + o] = w.x;
            Wt[(c4 + 1) * 132 + o] = w.y;
            Wt[(c4 + 2) * 132 + o] = w.z;
            Wt[(c4 + 3) * 132 + o] = w.w;
        }
        __syncthreads();
#pragma unroll 8
        for (int cc = 0; cc < 32; cc++) {
            float xv[4];
#pragma unroll
            for (int i = 0; i < 4; i++) xv[i] = Xs[cc * 68 + r0 + i];
            float4 wa = *(float4*)&Wt[cc * 132 + o0];
            float4 wb = *(float4*)&Wt[cc * 132 + o0 + 4];
            float wv[8] = {wa.x, wa.y, wa.z, wa.w, wb.x, wb.y, wb.z, wb.w};
#pragma unroll
            for (int i = 0; i < 4; i++)
#pragma unroll
                for (int j = 0; j < 8; j++) acc[i][j] += xv[i] * wv[j];
        }
    }

    float bv[8];
#pragma unroll
    for (int j = 0; j < 8; j++) bv[j] = b1[o0 + j];

    float nsum[4];
#pragma unroll
    for (int i = 0; i < 4; i++) {
        float v[8];
        float s = 0.f;
#pragma unroll
        for (int j = 0; j < 8; j++) {
            v[j] = acc[i][j] + bv[j];
            s += v[j] * v[j];
        }
        nsum[i] = s;
        uint32_t hw[4], lw[4];
#pragma unroll
        for (int e = 0; e < 4; e++) hw[e] = split2(v[2 * e], v[2 * e + 1], lw[e]);
        const size_t idx = (size_t)(b * N_ + n0 + r0 + i) * C2_ + o0;
        *(uint4*)(g_yhi + idx) = make_uint4(hw[0], hw[1], hw[2], hw[3]);
        *(uint4*)(g_ylo + idx) = make_uint4(lw[0], lw[1], lw[2], lw[3]);
    }

    // reduce norms over the 16 tx lanes (same ty = 16 consecutive lanes)
#pragma unroll
    for (int i = 0; i < 4; i++) {
#pragma unroll
        for (int off = 8; off > 0; off >>= 1)
            nsum[i] += __shfl_xor_sync(0xffffffffu, nsum[i], off);
    }
    if (tx == 0) {
        float mx = 0.f;
#pragma unroll
        for (int i = 0; i < 4; i++) {
            g_nrm[(size_t)b * N_ + n0 + r0 + i] = nsum[i];
            mx = fmaxf(mx, nsum[i]);
        }
        Rmx[ty] = mx;
    }
    __syncthreads();
    if (t == 0) {
        float mx = Rmx[0];
#pragma unroll
        for (int i = 1; i < 16; i++) mx = fmaxf(mx, Rmx[i]);
        atomicMax((int*)&g_R[b], __float_as_int(mx));
    }
}

// ---------------------------------------------------------------------------
// mma.sync flash attention, cp.async double-buffered K chunks.
// 8 warps; warp w owns query rows w*16..w*16+15. Q frags reloaded from smem
// (matches the proven 218-reg layout; no hoist, no spills).
// ---------------------------------------------------------------------------
__global__ __launch_bounds__(256, 1) void attn_mma_kernel() {
    extern __shared__ __align__(16) char sm[];
    const uint32_t sb = s2u(sm);

    const int t = threadIdx.x;
    const int w = t >> 5, lane = t & 31;
    const int n0 = blockIdx.x * QT;
    const int b  = blockIdx.y;
    const __nv_bfloat16* yhib = g_yhi + (size_t)b * N_ * C2_;
    const __nv_bfloat16* ylob = g_ylo + (size_t)b * N_ * C2_;

    // fixed softmax bases for this thread's two rows
    const int r0 = w * 16 + (lane >> 2);
    const int r1 = r0 + 8;
    const float Rb = g_R[b];
    const float mt0 = sqrtf(g_nrm[(size_t)b * N_ + n0 + r0] * Rb);
    const float mt1 = sqrtf(g_nrm[(size_t)b * N_ + n0 + r1] * Rb);

    // prefetch K chunk 0 into buf 0 (hi+lo), async
    {
        const int j = t >> 2, q = t & 3;
        const int j7 = j & 7;
        const __nv_bfloat16* srch = yhib + (size_t)j * C2_;
        const __nv_bfloat16* srcl = ylob + (size_t)j * C2_;
#pragma unroll
        for (int i = 0; i < 4; i++) {
            const int c16 = q * 4 + i;
            const uint32_t off = (uint32_t)j * 256 + ((c16 ^ j7) << 4);
            cpasync16(sb + OFF_KB + off,       srch + c16 * 8);
            cpasync16(sb + OFF_KB + KLO + off, srcl + c16 * 8);
        }
    }
    asm volatile("cp.async.commit_group;" ::: "memory");

    // ---- stage Q tile (pre-converted bf16) into resident smem ----
    {
        const int row = t >> 1, half = t & 1;
        const __nv_bfloat16* srch = yhib + (size_t)(n0 + row) * C2_;
        const __nv_bfloat16* srcl = ylob + (size_t)(n0 + row) * C2_;
        const int r7 = row & 7;
#pragma unroll
        for (int f = 0; f < 8; f++) {
            const int c16 = half * 8 + f;
            const uint32_t off = (uint32_t)row * 256 + ((c16 ^ r7) << 4);
            *(uint4*)(sm + OFF_QHI + off) = *(const uint4*)(srch + c16 * 8);
            *(uint4*)(sm + OFF_QLO + off) = *(const uint4*)(srcl + c16 * 8);
        }
    }
    __syncthreads();

    // ldmatrix lane-address precompute
    const int laneh = lane >> 4;
    const int rowA  = w * 16 + (lane & 15);
    const int rA7   = rowA & 7;
    const uint32_t aQhi = sb + OFF_QHI + (uint32_t)rowA * 256;
    const uint32_t aQlo = sb + OFF_QLO + (uint32_t)rowA * 256;
    const int keyS = (lane & 7) + (laneh << 3);
    const int cS   = (lane >> 3) & 1;
    const int l7   = lane & 7;
    const int keyV = lane & 15;

    float o[16][4];
#pragma unroll
    for (int n = 0; n < 16; n++)
#pragma unroll
        for (int e = 0; e < 4; e++) o[n][e] = 0.f;
    float lacc0 = 0.f, lacc1 = 0.f;

    for (int ci = 0; ci < NCHUNK; ci++) {
        __syncthreads();  // prior reads of the buffer about to be overwritten done

        // prefetch chunk ci+1 into the other buffer
        if (ci + 1 < NCHUNK) {
            const int j = t >> 2, q = t & 3;
            const int j7 = j & 7;
            const uint32_t base = sb + OFF_KB + (uint32_t)((ci + 1) & 1) * KBUF_SZ;
            const __nv_bfloat16* srch = yhib + (size_t)((ci + 1) * KT + j) * C2_;
            const __nv_bfloat16* srcl = ylob + (size_t)((ci + 1) * KT + j) * C2_;
#pragma unroll
            for (int i = 0; i < 4; i++) {
                const int c16 = q * 4 + i;
                const uint32_t off = (uint32_t)j * 256 + ((c16 ^ j7) << 4);
                cpasync16(base + off,       srch + c16 * 8);
                cpasync16(base + KLO + off, srcl + c16 * 8);
            }
            asm volatile("cp.async.commit_group;" ::: "memory");
            asm volatile("cp.async.wait_group 1;" ::: "memory");
        } else {
            asm volatile("cp.async.wait_group 0;" ::: "memory");
        }
        __syncthreads();  // chunk ci visible to all warps

        const uint32_t bufh = sb + OFF_KB + (uint32_t)(ci & 1) * KBUF_SZ;
        const uint32_t bufl = bufh + KLO;

        // ---- S = Q K^T : 3-pass hi/lo (Q frags reloaded per ktile) ----
        float s[8][4];
#pragma unroll
        for (int n = 0; n < 8; n++)
#pragma unroll
            for (int e = 0; e < 4; e++) s[n][e] = 0.f;

#pragma unroll
        for (int k = 0; k < 8; k++) {
            const int cA = 2 * k + laneh;
            uint32_t qh[4], ql[4];
            ldsm4(qh, aQhi + ((cA ^ rA7) << 4));
            ldsm4(ql, aQlo + ((cA ^ rA7) << 4));
            const int cB = 2 * k + cS;
#pragma unroll
            for (int np = 0; np < 4; np++) {
                const uint32_t rb = (uint32_t)(np * 16 + keyS) * 256 +
                                    (uint32_t)((cB ^ l7) << 4);
                uint32_t bh[4], bl[4];
                ldsm4(bh, bufh + rb);
                ldsm4(bl, bufl + rb);
                mma16816(s[2 * np],     qh, bh);
                mma16816(s[2 * np + 1], qh, bh + 2);
                mma16816(s[2 * np],     qh, bl);
                mma16816(s[2 * np + 1], qh, bl + 2);
                mma16816(s[2 * np],     ql, bh);
                mma16816(s[2 * np + 1], ql, bh + 2);
            }
        }

        // ---- softmax (fixed base) + pack P into A-fragments hi/lo ----
        uint32_t ph[16], pl[16];
#pragma unroll
        for (int j = 0; j < 8; j++) {
            float p0 = __expf(s[j][0] - mt0);
            float p1 = __expf(s[j][1] - mt0);
            float p2 = __expf(s[j][2] - mt1);
            float p3 = __expf(s[j][3] - mt1);
            lacc0 += p0 + p1;
            lacc1 += p2 + p3;
            const int idx = (j >> 1) * 4 + (j & 1) * 2;
            ph[idx]     = split2(p0, p1, pl[idx]);
            ph[idx + 1] = split2(p2, p3, pl[idx + 1]);
        }

        // ---- O += P V : V via ldmatrix.trans on the same K tile ----
#pragma unroll
        for (int fp = 0; fp < 8; fp++) {
#pragma unroll
            for (int K = 0; K < 4; K++) {
                const uint32_t rb = (uint32_t)(K * 16 + keyV) * 256 +
                                    (uint32_t)(((fp * 2 + laneh) ^ l7) << 4);
                uint32_t vh[4], vl[4];
                ldsm4t(vh, bufh + rb);
                ldsm4t(vl, bufl + rb);
                mma16816(o[2 * fp],     &ph[4 * K], vh);
                mma16816(o[2 * fp + 1], &ph[4 * K], vh + 2);
                mma16816(o[2 * fp],     &ph[4 * K], vl);
                mma16816(o[2 * fp + 1], &ph[4 * K], vl + 2);
                mma16816(o[2 * fp],     &pl[4 * K], vh);
                mma16816(o[2 * fp + 1], &pl[4 * K], vh + 2);
            }
        }
    }

    // ---- finalize l ----
    lacc0 += __shfl_xor_sync(0xffffffffu, lacc0, 1);
    lacc0 += __shfl_xor_sync(0xffffffffu, lacc0, 2);
    lacc1 += __shfl_xor_sync(0xffffffffu, lacc1, 1);
    lacc1 += __shfl_xor_sync(0xffffffffu, lacc1, 2);
    const float inv0 = 1.0f / lacc0;
    const float inv1 = 1.0f / lacc1;

    // ---- epilogue: normalize, store flat [n][c2] (torch-bug order) ----
    float* dst0 = g_att + (size_t)b * N_ * C2_ + (size_t)(n0 + r0) * C2_;
    float* dst1 = g_att + (size_t)b * N_ * C2_ + (size_t)(n0 + r1) * C2_;
    const int fbase = 2 * (lane & 3);
#pragma unroll
    for (int n = 0; n < 16; n++) {
        const int f = n * 8 + fbase;
        *(float2*)(dst0 + f) = make_float2(o[n][0] * inv0, o[n][1] * inv0);
        *(float2*)(dst1 + f) = make_float2(o[n][2] * inv1, o[n][3] * inv1);
    }
}

// ---------------------------------------------------------------------------
// conv2 + scale + residual
// ---------------------------------------------------------------------------
__global__ __launch_bounds__(256) void conv2_kernel(const float* __restrict__ x,
                                                    const float* __restrict__ W2,
                                                    const float* __restrict__ b2,
                                                    const float* __restrict__ scale,
                                                    float* __restrict__ out) {
    extern __shared__ float smf[];
    float* Ss = smf;
    float* Ws = smf + 128 * 68;

    const int t  = threadIdx.x;
    const int n0 = blockIdx.x * 64;
    const int o0 = blockIdx.y * 64;
    const int b  = blockIdx.z;
    const int ty = t >> 4, tx = t & 15;
    const int r0 = ty * 4;
    const int c0 = tx * 4;
    const float* sbp = g_att + (size_t)b * N_ * C2_;

    for (int e = t; e < 128 * 16; e += 256) {
        int row = e >> 4, k4 = (e & 15) << 2;
        *(float4*)&Ss[row * 68 + k4] = *(const float4*)(sbp + (size_t)row * N_ + n0 + k4);
    }
    for (int e = t; e < 64 * 32; e += 256) {
        int o = e >> 5, c4 = (e & 31) << 2;
        *(float4*)&Ws[o * 132 + c4] = *(const float4*)(W2 + (size_t)(o0 + o) * C2_ + c4);
    }
    __syncthreads();

    float acc[4][4];
#pragma unroll
    for (int i = 0; i < 4; i++)
#pragma unroll
        for (int j = 0; j < 4; j++) acc[i][j] = 0.f;

#pragma unroll 4
    for (int c = 0; c < 128; c++) {
        float wv[4];
#pragma unroll
        for (int i = 0; i < 4; i++) wv[i] = Ws[(r0 + i) * 132 + c];
        float4 sv = *(float4*)&Ss[c * 68 + c0];
#pragma unroll
        for (int i = 0; i < 4; i++) {
            acc[i][0] += wv[i] * sv.x;
            acc[i][1] += wv[i] * sv.y;
            acc[i][2] += wv[i] * sv.z;
            acc[i][3] += wv[i] * sv.w;
        }
    }

#pragma unroll
    for (int i = 0; i < 4; i++) {
        int oo = o0 + r0 + i;
        float sc = scale[oo];
        float bi = b2[oo];
        size_t idx = ((size_t)(b * C_ + oo)) * N_ + n0 + c0;
        float4 xv = *(const float4*)(x + idx);
        float4 r;
        r.x = sc * (acc[i][0] + bi) + xv.x;
        r.y = sc * (acc[i][1] + bi) + xv.y;
        r.z = sc * (acc[i][2] + bi) + xv.z;
        r.w = sc * (acc[i][3] + bi) + xv.w;
        *(float4*)(out + idx) = r;
    }
}

// ---------------------------------------------------------------------------
extern "C" void kernel_launch(void* const* d_in, const int* in_sizes, int n_in,
                              void* d_out, int out_size) {
    const float* x     = (const float*)d_in[0];
    const float* W1    = (const float*)d_in[1];
    const float* b1    = (const float*)d_in[2];
    const float* W2    = (const float*)d_in[3];
    const float* b2    = (const float*)d_in[4];
    const float* scale = (const float*)d_in[5];
    float* out = (float*)d_out;

    constexpr int CONV2_SMEM = (128 * 68 + 64 * 132) * 4;
    cudaFuncSetAttribute(attn_mma_kernel, cudaFuncAttributeMaxDynamicSharedMemorySize, ATTN_DYN);
    cudaFuncSetAttribute(conv2_kernel, cudaFuncAttributeMaxDynamicSharedMemorySize, CONV2_SMEM);

    init_kernel<<<1, 32>>>();
    conv1_kernel<<<dim3(N_ / 64, B_), 256>>>(x, W1, b1);
    attn_mma_kernel<<<dim3(N_ / QT, B_), 256, ATTN_DYN>>>();
    conv2_kernel<<<dim3(N_ / 64, C_ / 64, B_), 256, CONV2_SMEM>>>(x, W2, b2, scale, out);
}

// round 17
// speedup vs baseline: 1.7347x; 1.0971x over previous
#include <cuda_runtime.h>
#include <cuda_fp16.h>
#include <cstdint>

// NonLocalBlock on GB300 (plain sm_103 ISA): conv1(1x1, fused fp16 hi/lo split)
// -> flash self-attention via mma.sync fp16 HMMA:
//   S = QK^T in 3-pass hi/lo fp16 (fp32-grade logits),
//   ONLINE softmax (register-resident O -> rescale is cheap; keeps p in [~0,1]
//   so fp16 never underflows — the R16 failure mode),
//   P*V in single pass fp16 (2^-12 rounding -> ~2e-4 final rel err per R13
//   calibration), cp.async double-buffered 128-key chunks
// -> conv2 + scale + residual.  B=8, C=256, C2=128, N=4096, fp32 I/O.

namespace {
constexpr int B_  = 8;
constexpr int C_  = 256;
constexpr int C2_ = 128;
constexpr int N_  = 4096;
constexpr int QT  = 128;          // queries per block
constexpr int KT2 = 128;          // keys per load chunk (2 x 64-key halves)
constexpr int NCHUNK2 = N_ / KT2; // 32

// attention smem (bytes): resident Q hi/lo + double-buffered 128-key chunk
// hi/lo. row stride 256B (128 feats fp16), 16B chunks XOR-swizzled by (row&7).
constexpr int OFF_QHI = 0;             // 128 x 256B = 32KB
constexpr int OFF_QLO = 32768;         // 32KB
constexpr int OFF_KB  = 65536;         // 2 bufs x (32KB hi + 32KB lo)
constexpr int KBUF_SZ = 65536;
constexpr int KLO     = 32768;         // lo offset within a buf
constexpr int HALF_SZ = 16384;         // 64 rows x 256B, offset of key-half 1
constexpr int ATTN_DYN = OFF_KB + 2 * KBUF_SZ;   // 196608
}

__device__ __half g_yhi[B_ * N_ * C2_];  // conv1 out, hi fp16, [b][n][c2]
__device__ __half g_ylo[B_ * N_ * C2_];  // residual lo fp16
__device__ float g_att[B_ * N_ * C2_];   // attention out (torch-bug flat order)

// ---------------------------------------------------------------------------
// helpers
// ---------------------------------------------------------------------------
__device__ __forceinline__ uint32_t s2u(const void* p) {
    uint32_t a;
    asm("{ .reg .u64 t; cvta.to.shared.u64 t, %1; cvt.u32.u64 %0, t; }" : "=r"(a) : "l"(p));
    return a;
}

__device__ __forceinline__ uint32_t packh(__half a, __half b) {
    __half2 t = __halves2half2(a, b);
    return *reinterpret_cast<uint32_t*>(&t);
}

// fp16 hi/lo split of a float pair -> two packed half2
__device__ __forceinline__ uint32_t split2h(float a, float b, uint32_t& lo) {
    __half ha = __float2half(a), hb = __float2half(b);
    lo = packh(__float2half(a - __half2float(ha)),
               __float2half(b - __half2float(hb)));
    return packh(ha, hb);
}

__device__ __forceinline__ void ldsm4(uint32_t* r, uint32_t addr) {
    asm volatile("ldmatrix.sync.aligned.m8n8.x4.shared.b16 {%0,%1,%2,%3}, [%4];"
                 : "=r"(r[0]), "=r"(r[1]), "=r"(r[2]), "=r"(r[3]) : "r"(addr));
}

__device__ __forceinline__ void ldsm4t(uint32_t* r, uint32_t addr) {
    asm volatile("ldmatrix.sync.aligned.m8n8.x4.trans.shared.b16 {%0,%1,%2,%3}, [%4];"
                 : "=r"(r[0]), "=r"(r[1]), "=r"(r[2]), "=r"(r[3]) : "r"(addr));
}

__device__ __forceinline__ void mma16816(float* d, const uint32_t* a, const uint32_t* b) {
    asm volatile(
        "mma.sync.aligned.m16n8k16.row.col.f32.f16.f16.f32 "
        "{%0,%1,%2,%3}, {%4,%5,%6,%7}, {%8,%9}, {%0,%1,%2,%3};"
        : "+f"(d[0]), "+f"(d[1]), "+f"(d[2]), "+f"(d[3])
        : "r"(a[0]), "r"(a[1]), "r"(a[2]), "r"(a[3]), "r"(b[0]), "r"(b[1]));
}

__device__ __forceinline__ void cpasync16(uint32_t saddr, const void* gaddr) {
    asm volatile("cp.async.cg.shared.global [%0], [%1], 16;"
                 :: "r"(saddr), "l"(gaddr) : "memory");
}

// ---------------------------------------------------------------------------
// conv1: y[b][n][o] = b1[o] + sum_c x[b][c][n] * W1[o][c]
// Epilogue: fp16 hi/lo split to g_yhi/g_ylo.
// ---------------------------------------------------------------------------
__global__ __launch_bounds__(256) void conv1_kernel(const float* __restrict__ x,
                                                    const float* __restrict__ W1,
                                                    const float* __restrict__ b1) {
    __shared__ float Xs[32 * 68];
    __shared__ float Wt[32 * 132];

    const int t  = threadIdx.x;
    const int n0 = blockIdx.x * 64;
    const int b  = blockIdx.y;
    const int ty = t >> 4, tx = t & 15;
    const int r0 = ty * 4;
    const int o0 = tx * 8;
    const float* xb = x + (size_t)b * C_ * N_;

    float acc[4][8];
#pragma unroll
    for (int i = 0; i < 4; i++)
#pragma unroll
        for (int j = 0; j < 8; j++) acc[i][j] = 0.f;

    for (int c0 = 0; c0 < C_; c0 += 32) {
        __syncthreads();
        for (int e = t; e < 32 * 16; e += 256) {
            int cc = e >> 4, k4 = (e & 15) << 2;
            *(float4*)&Xs[cc * 68 + k4] =
                *(const float4*)(xb + (size_t)(c0 + cc) * N_ + n0 + k4);
        }
        for (int e = t; e < 128 * 8; e += 256) {
            int o = e >> 3, c4 = (e & 7) << 2;
            float4 w = *(const float4*)(W1 + (size_t)o * C_ + c0 + c4);
            Wt[(c4 + 0) * 132 + o] = w.x;
            Wt[(c4 + 1) * 132 + o] = w.y;
            Wt[(c4 + 2) * 132 + o] = w.z;
            Wt[(c4 + 3) * 132 + o] = w.w;
        }
        __syncthreads();
#pragma unroll 8
        for (int cc = 0; cc < 32; cc++) {
            float xv[4];
#pragma unroll
            for (int i = 0; i < 4; i++) xv[i] = Xs[cc * 68 + r0 + i];
            float4 wa = *(float4*)&Wt[cc * 132 + o0];
            float4 wb = *(float4*)&Wt[cc * 132 + o0 + 4];
            float wv[8] = {wa.x, wa.y, wa.z, wa.w, wb.x, wb.y, wb.z, wb.w};
#pragma unroll
            for (int i = 0; i < 4; i++)
#pragma unroll
                for (int j = 0; j < 8; j++) acc[i][j] += xv[i] * wv[j];
        }
    }

    float bv[8];
#pragma unroll
    for (int j = 0; j < 8; j++) bv[j] = b1[o0 + j];

#pragma unroll
    for (int i = 0; i < 4; i++) {
        float v[8];
#pragma unroll
        for (int j = 0; j < 8; j++) v[j] = acc[i][j] + bv[j];
        uint32_t hw[4], lw[4];
#pragma unroll
        for (int e = 0; e < 4; e++) hw[e] = split2h(v[2 * e], v[2 * e + 1], lw[e]);
        const size_t idx = (size_t)(b * N_ + n0 + r0 + i) * C2_ + o0;
        *(uint4*)(g_yhi + idx) = make_uint4(hw[0], hw[1], hw[2], hw[3]);
        *(uint4*)(g_ylo + idx) = make_uint4(lw[0], lw[1], lw[2], lw[3]);
    }
}

// ---------------------------------------------------------------------------
// mma.sync fp16 flash attention, cp.async double-buffered 128-key chunks
// processed as two 64-key halves. S: 3-pass hi/lo fp16. ONLINE softmax with
// register-O rescale. PV: single pass fp16(P) x fp16-hi(V).
// ---------------------------------------------------------------------------
__global__ __launch_bounds__(256, 1) void attn_mma_kernel() {
    extern __shared__ __align__(16) char sm[];
    const uint32_t sb = s2u(sm);

    const int t = threadIdx.x;
    const int w = t >> 5, lane = t & 31;
    const int n0 = blockIdx.x * QT;
    const int b  = blockIdx.y;
    const __half* yhib = g_yhi + (size_t)b * N_ * C2_;
    const __half* ylob = g_ylo + (size_t)b * N_ * C2_;

    // this thread's two query rows
    const int r0 = w * 16 + (lane >> 2);
    const int r1 = r0 + 8;

    // chunk loader mapping: 2 threads per key row, 8 c16 chunks each (hi+lo)
    const int kj = t >> 1, khalf = t & 1;
    const int kj7 = kj & 7;

    // prefetch K chunk 0 into buf 0 (hi+lo), async
    {
        const __half* srch = yhib + (size_t)kj * C2_;
        const __half* srcl = ylob + (size_t)kj * C2_;
#pragma unroll
        for (int i = 0; i < 8; i++) {
            const int c16 = khalf * 8 + i;
            const uint32_t off = (uint32_t)kj * 256 + ((c16 ^ kj7) << 4);
            cpasync16(sb + OFF_KB + off,       srch + c16 * 8);
            cpasync16(sb + OFF_KB + KLO + off, srcl + c16 * 8);
        }
    }
    asm volatile("cp.async.commit_group;" ::: "memory");

    // ---- stage Q tile (pre-converted fp16) into resident smem ----
    {
        const int row = t >> 1, half = t & 1;
        const __half* srch = yhib + (size_t)(n0 + row) * C2_;
        const __half* srcl = ylob + (size_t)(n0 + row) * C2_;
        const int r7 = row & 7;
#pragma unroll
        for (int f = 0; f < 8; f++) {
            const int c16 = half * 8 + f;
            const uint32_t off = (uint32_t)row * 256 + ((c16 ^ r7) << 4);
            *(uint4*)(sm + OFF_QHI + off) = *(const uint4*)(srch + c16 * 8);
            *(uint4*)(sm + OFF_QLO + off) = *(const uint4*)(srcl + c16 * 8);
        }
    }
    __syncthreads();

    // ldmatrix lane-address precompute
    const int laneh = lane >> 4;
    const int rowA  = w * 16 + (lane & 15);
    const int rA7   = rowA & 7;
    const uint32_t aQhi = sb + OFF_QHI + (uint32_t)rowA * 256;
    const uint32_t aQlo = sb + OFF_QLO + (uint32_t)rowA * 256;
    const int keyS = (lane & 7) + (laneh << 3);
    const int cS   = (lane >> 3) & 1;
    const int l7   = lane & 7;
    const int keyV = lane & 15;

    float o[16][4];
#pragma unroll
    for (int n = 0; n < 16; n++)
#pragma unroll
        for (int e = 0; e < 4; e++) o[n][e] = 0.f;
    float lacc0 = 0.f, lacc1 = 0.f;
    float m0 = -1e30f, m1 = -1e30f;   // running row maxima

    for (int ci = 0; ci < NCHUNK2; ci++) {
        __syncthreads();  // prior reads of the buffer about to be overwritten done

        // prefetch chunk ci+1 into the other buffer
        if (ci + 1 < NCHUNK2) {
            const uint32_t base = sb + OFF_KB + (uint32_t)((ci + 1) & 1) * KBUF_SZ;
            const __half* srch = yhib + (size_t)((ci + 1) * KT2 + kj) * C2_;
            const __half* srcl = ylob + (size_t)((ci + 1) * KT2 + kj) * C2_;
#pragma unroll
            for (int i = 0; i < 8; i++) {
                const int c16 = khalf * 8 + i;
                const uint32_t off = (uint32_t)kj * 256 + ((c16 ^ kj7) << 4);
                cpasync16(base + off,       srch + c16 * 8);
                cpasync16(base + KLO + off, srcl + c16 * 8);
            }
            asm volatile("cp.async.commit_group;" ::: "memory");
            asm volatile("cp.async.wait_group 1;" ::: "memory");
        } else {
            asm volatile("cp.async.wait_group 0;" ::: "memory");
        }
        __syncthreads();  // chunk ci visible to all warps

        const uint32_t cbase = sb + OFF_KB + (uint32_t)(ci & 1) * KBUF_SZ;

        // ---- two 64-key halves within the chunk (no barriers needed) ----
#pragma unroll 1
        for (int h = 0; h < 2; h++) {
            const uint32_t bufh = cbase + (uint32_t)h * HALF_SZ;
            const uint32_t bufl = bufh + KLO;

            // ---- S = Q K^T : 3-pass hi/lo fp16 ----
            float s[8][4];
#pragma unroll
            for (int n = 0; n < 8; n++)
#pragma unroll
                for (int e = 0; e < 4; e++) s[n][e] = 0.f;

#pragma unroll
            for (int k = 0; k < 8; k++) {
                const int cA = 2 * k + laneh;
                uint32_t qh[4], ql[4];
                ldsm4(qh, aQhi + ((cA ^ rA7) << 4));
                ldsm4(ql, aQlo + ((cA ^ rA7) << 4));
                const int cB = 2 * k + cS;
#pragma unroll
                for (int np = 0; np < 4; np++) {
                    const uint32_t rb = (uint32_t)(np * 16 + keyS) * 256 +
                                        (uint32_t)((cB ^ l7) << 4);
                    uint32_t bh[4], bl[4];
                    ldsm4(bh, bufh + rb);
                    ldsm4(bl, bufl + rb);
                    mma16816(s[2 * np],     qh, bh);
                    mma16816(s[2 * np + 1], qh, bh + 2);
                    mma16816(s[2 * np],     qh, bl);
                    mma16816(s[2 * np + 1], qh, bl + 2);
                    mma16816(s[2 * np],     ql, bh);
                    mma16816(s[2 * np + 1], ql, bh + 2);
                }
            }

            // ---- online softmax: chunk max -> rescale O,l -> p in (0,1] ----
            float mc0 = s[0][0], mc1 = s[0][2];
#pragma unroll
            for (int j = 0; j < 8; j++) {
                mc0 = fmaxf(mc0, fmaxf(s[j][0], s[j][1]));
                mc1 = fmaxf(mc1, fmaxf(s[j][2], s[j][3]));
            }
            mc0 = fmaxf(mc0, __shfl_xor_sync(0xffffffffu, mc0, 1));
            mc0 = fmaxf(mc0, __shfl_xor_sync(0xffffffffu, mc0, 2));
            mc1 = fmaxf(mc1, __shfl_xor_sync(0xffffffffu, mc1, 1));
            mc1 = fmaxf(mc1, __shfl_xor_sync(0xffffffffu, mc1, 2));
            const float mn0 = fmaxf(m0, mc0), mn1 = fmaxf(m1, mc1);
            const float f0 = __expf(m0 - mn0), f1 = __expf(m1 - mn1);
            m0 = mn0; m1 = mn1;
            lacc0 *= f0; lacc1 *= f1;
#pragma unroll
            for (int n = 0; n < 16; n++) {
                o[n][0] *= f0; o[n][1] *= f0;
                o[n][2] *= f1; o[n][3] *= f1;
            }

            uint32_t ph[16];
#pragma unroll
            for (int j = 0; j < 8; j++) {
                float p0 = __expf(s[j][0] - m0);
                float p1 = __expf(s[j][1] - m0);
                float p2 = __expf(s[j][2] - m1);
                float p3 = __expf(s[j][3] - m1);
                lacc0 += p0 + p1;
                lacc1 += p2 + p3;
                const int idx = (j >> 1) * 4 + (j & 1) * 2;
                ph[idx]     = packh(__float2half(p0), __float2half(p1));
                ph[idx + 1] = packh(__float2half(p2), __float2half(p3));
            }

            // ---- O += P V(hi) : V via ldmatrix.trans on the same K tile ----
#pragma unroll
            for (int fp = 0; fp < 8; fp++) {
#pragma unroll
                for (int K = 0; K < 4; K++) {
                    const uint32_t rb = (uint32_t)(K * 16 + keyV) * 256 +
                                        (uint32_t)(((fp * 2 + laneh) ^ l7) << 4);
                    uint32_t vh[4];
                    ldsm4t(vh, bufh + rb);
                    mma16816(o[2 * fp],     &ph[4 * K], vh);
                    mma16816(o[2 * fp + 1], &ph[4 * K], vh + 2);
                }
            }
        }
    }

    // ---- finalize l (sum across the 4 quad lanes) ----
    lacc0 += __shfl_xor_sync(0xffffffffu, lacc0, 1);
    lacc0 += __shfl_xor_sync(0xffffffffu, lacc0, 2);
    lacc1 += __shfl_xor_sync(0xffffffffu, lacc1, 1);
    lacc1 += __shfl_xor_sync(0xffffffffu, lacc1, 2);
    const float inv0 = 1.0f / lacc0;
    const float inv1 = 1.0f / lacc1;

    // ---- epilogue: normalize, store flat [n][c2] (torch-bug order) ----
    float* dst0 = g_att + (size_t)b * N_ * C2_ + (size_t)(n0 + r0) * C2_;
    float* dst1 = g_att + (size_t)b * N_ * C2_ + (size_t)(n0 + r1) * C2_;
    const int fbase = 2 * (lane & 3);
#pragma unroll
    for (int n = 0; n < 16; n++) {
        const int f = n * 8 + fbase;
        *(float2*)(dst0 + f) = make_float2(o[n][0] * inv0, o[n][1] * inv0);
        *(float2*)(dst1 + f) = make_float2(o[n][2] * inv1, o[n][3] * inv1);
    }
}

// ---------------------------------------------------------------------------
// conv2 + scale + residual
// ---------------------------------------------------------------------------
__global__ __launch_bounds__(256) void conv2_kernel(const float* __restrict__ x,
                                                    const float* __restrict__ W2,
                                                    const float* __restrict__ b2,
                                                    const float* __restrict__ scale,
                                                    float* __restrict__ out) {
    extern __shared__ float smf[];
    float* Ss = smf;
    float* Ws = smf + 128 * 68;

    const int t  = threadIdx.x;
    const int n0 = blockIdx.x * 64;
    const int o0 = blockIdx.y * 64;
    const int b  = blockIdx.z;
    const int ty = t >> 4, tx = t & 15;
    const int r0 = ty * 4;
    const int c0 = tx * 4;
    const float* sbp = g_att + (size_t)b * N_ * C2_;

    for (int e = t; e < 128 * 16; e += 256) {
        int row = e >> 4, k4 = (e & 15) << 2;
        *(float4*)&Ss[row * 68 + k4] = *(const float4*)(sbp + (size_t)row * N_ + n0 + k4);
    }
    for (int e = t; e < 64 * 32; e += 256) {
        int o = e >> 5, c4 = (e & 31) << 2;
        *(float4*)&Ws[o * 132 + c4] = *(const float4*)(W2 + (size_t)(o0 + o) * C2_ + c4);
    }
    __syncthreads();

    float acc[4][4];
#pragma unroll
    for (int i = 0; i < 4; i++)
#pragma unroll
        for (int j = 0; j < 4; j++) acc[i][j] = 0.f;

#pragma unroll 4
    for (int c = 0; c < 128; c++) {
        float wv[4];
#pragma unroll
        for (int i = 0; i < 4; i++) wv[i] = Ws[(r0 + i) * 132 + c];
        float4 sv = *(float4*)&Ss[c * 68 + c0];
#pragma unroll
        for (int i = 0; i < 4; i++) {
            acc[i][0] += wv[i] * sv.x;
            acc[i][1] += wv[i] * sv.y;
            acc[i][2] += wv[i] * sv.z;
            acc[i][3] += wv[i] * sv.w;
        }
    }

#pragma unroll
    for (int i = 0; i < 4; i++) {
        int oo = o0 + r0 + i;
        float sc = scale[oo];
        float bi = b2[oo];
        size_t idx = ((size_t)(b * C_ + oo)) * N_ + n0 + c0;
        float4 xv = *(const float4*)(x + idx);
        float4 r;
        r.x = sc * (acc[i][0] + bi) + xv.x;
        r.y = sc * (acc[i][1] + bi) + xv.y;
        r.z = sc * (acc[i][2] + bi) + xv.z;
        r.w = sc * (acc[i][3] + bi) + xv.w;
        *(float4*)(out + idx) = r;
    }
}

// ---------------------------------------------------------------------------
extern "C" void kernel_launch(void* const* d_in, const int* in_sizes, int n_in,
                              void* d_out, int out_size) {
    const float* x     = (const float*)d_in[0];
    const float* W1    = (const float*)d_in[1];
    const float* b1    = (const float*)d_in[2];
    const float* W2    = (const float*)d_in[3];
    const float* b2    = (const float*)d_in[4];
    const float* scale = (const float*)d_in[5];
    float* out = (float*)d_out;

    constexpr int CONV2_SMEM = (128 * 68 + 64 * 132) * 4;
    cudaFuncSetAttribute(attn_mma_kernel, cudaFuncAttributeMaxDynamicSharedMemorySize, ATTN_DYN);
    cudaFuncSetAttribute(conv2_kernel, cudaFuncAttributeMaxDynamicSharedMemorySize, CONV2_SMEM);

    conv1_kernel<<<dim3(N_ / 64, B_), 256>>>(x, W1, b1);
    attn_mma_kernel<<<dim3(N_ / QT, B_), 256, ATTN_DYN>>>();
    conv2_kernel<<<dim3(N_ / 64, C_ / 64, B_), 256, CONV2_SMEM>>>(x, W2, b2, scale, out);
}